// round 1
// baseline (speedup 1.0000x reference)
#include <cuda_runtime.h>
#include <cstdint>

#define Nn  50000
#define NTt 300000
#define RPk 16
#define Ee  32
#define Cc  32

// ------------------------- device scratch (static, no allocs) -------------
__device__ float g_lat1[(size_t)NTt * RPk];        // 19.2 MB
__device__ float g_lat2[(size_t)NTt * RPk];        // 19.2 MB
__device__ float g_colsum[Nn * RPk];               // 3.2 MB
__device__ float g_rowsum[Nn * RPk];               // 3.2 MB
__device__ float g_invcol[Nn * RPk];
__device__ float g_invrow[Nn * RPk];
__device__ float g_h[Nn * Ee];                     // 6.4 MB
__device__ float g_h2[(size_t)RPk * Nn * Ee];      // 102.4 MB
__device__ int   g_deg[Nn];
__device__ int   g_off[Nn + 1];
__device__ int   g_cur[Nn];
__device__ int   g_perm[NTt];

// ------------------------- small helpers ----------------------------------
__device__ __forceinline__ unsigned long long splat2(float v) {
    unsigned long long r;
    asm("mov.b64 %0, {%1, %1};" : "=l"(r) : "f"(v));
    return r;
}
__device__ __forceinline__ unsigned long long ffma2(unsigned long long a,
                                                    unsigned long long b,
                                                    unsigned long long c) {
    unsigned long long d;
    asm("fma.rn.f32x2 %0, %1, %2, %3;" : "=l"(d) : "l"(a), "l"(b), "l"(c));
    return d;
}
__device__ __forceinline__ void red4(float4* a, float4 v) {
    asm volatile("red.global.add.v4.f32 [%0], {%1, %2, %3, %4};"
                 :: "l"(a), "f"(v.x), "f"(v.y), "f"(v.z), "f"(v.w) : "memory");
}

// ------------------------- init: zero scratch -----------------------------
__global__ void k_init() {
    size_t i = (size_t)blockIdx.x * blockDim.x + threadIdx.x;
    size_t stride = (size_t)gridDim.x * blockDim.x;
    float4 z = make_float4(0.f, 0.f, 0.f, 0.f);
    for (size_t p = i; p < (size_t)RPk * Nn * Ee / 4; p += stride)
        ((float4*)g_h2)[p] = z;
    for (size_t p = i; p < (size_t)Nn * RPk / 4; p += stride) {
        ((float4*)g_colsum)[p] = z;
        ((float4*)g_rowsum)[p] = z;
    }
    for (size_t p = i; p < (size_t)Nn * Ee / 4; p += stride)
        ((float4*)g_h)[p] = z;
    for (size_t p = i; p < Nn / 4; p += stride)
        ((int4*)g_deg)[p] = make_int4(0, 0, 0, 0);
}

// ------------------------- per-edge MLPs + softmax + segment sums ---------
__device__ __forceinline__ void mlp16(const float* __restrict__ x,
                                      const float* __restrict__ Wa,
                                      const float* __restrict__ ba,
                                      const float* __restrict__ Wb,
                                      const float* __restrict__ bb,
                                      float* __restrict__ lat) {
    unsigned long long hid[32];
#pragma unroll
    for (int j = 0; j < 32; j++) hid[j] = ((const unsigned long long*)ba)[j];
#pragma unroll
    for (int i = 0; i < 64; i++) {
        unsigned long long xs = splat2(x[i]);
        const unsigned long long* wr = (const unsigned long long*)(Wa + i * 64);
#pragma unroll
        for (int j = 0; j < 32; j++) hid[j] = ffma2(xs, wr[j], hid[j]);
    }
    unsigned long long acc[8];
#pragma unroll
    for (int k = 0; k < 8; k++) acc[k] = ((const unsigned long long*)bb)[k];
#pragma unroll
    for (int j = 0; j < 32; j++) {
        float2 hv = *(float2*)&hid[j];
        unsigned long long s0 = splat2(fmaxf(hv.x, 0.f));
        unsigned long long s1 = splat2(fmaxf(hv.y, 0.f));
        const unsigned long long* w0 = (const unsigned long long*)(Wb + (2 * j) * 16);
        const unsigned long long* w1 = (const unsigned long long*)(Wb + (2 * j + 1) * 16);
#pragma unroll
        for (int k = 0; k < 8; k++) acc[k] = ffma2(s1, w1[k], ffma2(s0, w0[k], acc[k]));
    }
#pragma unroll
    for (int k = 0; k < 8; k++) {
        float2 v = *(float2*)&acc[k];
        lat[2 * k] = v.x;
        lat[2 * k + 1] = v.y;
    }
}

__device__ __forceinline__ void softmax16(float* l) {
    float m = l[0];
#pragma unroll
    for (int k = 1; k < 16; k++) m = fmaxf(m, l[k]);
    float s = 0.f;
#pragma unroll
    for (int k = 0; k < 16; k++) { l[k] = __expf(l[k] - m); s += l[k]; }
    float inv = 1.f / s;
#pragma unroll
    for (int k = 0; k < 16; k++) l[k] *= inv;
}

__global__ void __launch_bounds__(256)
k_mlp(const int* __restrict__ s_idx, const int* __restrict__ o_idx,
      const float* __restrict__ nhots,
      const float* __restrict__ W1a, const float* __restrict__ b1a,
      const float* __restrict__ W1b, const float* __restrict__ b1b,
      const float* __restrict__ W2a, const float* __restrict__ b2a,
      const float* __restrict__ W2b, const float* __restrict__ b2b) {
    __shared__ __align__(16) float sW1a[64 * 64];
    __shared__ __align__(16) float sW1b[64 * 16];
    __shared__ __align__(16) float sW2a[64 * 64];
    __shared__ __align__(16) float sW2b[64 * 16];
    __shared__ __align__(16) float sb1a[64], sb2a[64];
    __shared__ __align__(16) float sb1b[16], sb2b[16];
    __shared__ float swr1[8], swr2[8];

    int tid = threadIdx.x;
    for (int i = tid; i < 64 * 64; i += 256) { sW1a[i] = W1a[i]; sW2a[i] = W2a[i]; }
    for (int i = tid; i < 64 * 16; i += 256) { sW1b[i] = W1b[i]; sW2b[i] = W2b[i]; }
    if (tid < 64) { sb1a[tid] = b1a[tid]; sb2a[tid] = b2a[tid]; }
    if (tid < 16) { sb1b[tid] = b1b[tid]; sb2b[tid] = b2b[tid]; }
    __syncthreads();

    int t = blockIdx.x * 256 + tid;
    float l1_0 = 0.f, l2_0 = 0.f;
    if (t < NTt) {
        float x[64];
        const float4* nh4 = (const float4*)(nhots + (size_t)t * 64);
#pragma unroll
        for (int i = 0; i < 16; i++) {
            float4 v = nh4[i];
            x[4 * i] = v.x; x[4 * i + 1] = v.y; x[4 * i + 2] = v.z; x[4 * i + 3] = v.w;
        }
        int s = s_idx[t], o = o_idx[t];

        float l1[16], l2[16];
        mlp16(x, sW1a, sb1a, sW1b, sb1b, l1);
        mlp16(x, sW2a, sb2a, sW2b, sb2b, l2);
        softmax16(l1);
        softmax16(l2);

        float4* p1 = (float4*)&g_lat1[(size_t)t * 16];
        float4* p2 = (float4*)&g_lat2[(size_t)t * 16];
#pragma unroll
        for (int q = 0; q < 4; q++) {
            p1[q] = make_float4(l1[4 * q], l1[4 * q + 1], l1[4 * q + 2], l1[4 * q + 3]);
            p2[q] = make_float4(l2[4 * q], l2[4 * q + 1], l2[4 * q + 2], l2[4 * q + 3]);
        }
#pragma unroll
        for (int k = 1; k < 16; k++) {
            atomicAdd(&g_colsum[o * k], l1[k]);
            atomicAdd(&g_rowsum[s * k], l2[k]);
        }
        l1_0 = l1[0];
        l2_0 = l2[0];
        atomicAdd(&g_deg[s], 1);
    }
    // block-reduce the k=0 contributions (all hit bin 0)
#pragma unroll
    for (int off = 16; off; off >>= 1) {
        l1_0 += __shfl_down_sync(0xffffffffu, l1_0, off);
        l2_0 += __shfl_down_sync(0xffffffffu, l2_0, off);
    }
    int wid = tid >> 5, lane = tid & 31;
    if (lane == 0) { swr1[wid] = l1_0; swr2[wid] = l2_0; }
    __syncthreads();
    if (tid == 0) {
        float a = 0.f, b = 0.f;
#pragma unroll
        for (int i = 0; i < 8; i++) { a += swr1[i]; b += swr2[i]; }
        atomicAdd(&g_colsum[0], a);
        atomicAdd(&g_rowsum[0], b);
    }
}

// ------------------------- CSR build: scan + scatter -----------------------
__global__ void k_scan() {
    __shared__ int ssum[1024];
    __shared__ int sbase;
    int tid = threadIdx.x;
    if (tid == 0) sbase = 0;
    __syncthreads();
    for (int base = 0; base < Nn; base += 1024) {
        int i = base + tid;
        int v = (i < Nn) ? g_deg[i] : 0;
        ssum[tid] = v;
        __syncthreads();
        for (int off = 1; off < 1024; off <<= 1) {
            int add = (tid >= off) ? ssum[tid - off] : 0;
            __syncthreads();
            ssum[tid] += add;
            __syncthreads();
        }
        int excl = ssum[tid] - v + sbase;
        if (i < Nn) { g_off[i] = excl; g_cur[i] = excl; }
        __syncthreads();
        if (tid == 1023) sbase += ssum[1023];
        __syncthreads();
    }
    if (tid == 0) g_off[Nn] = sbase;
}

__global__ void k_scatter(const int* __restrict__ s_idx) {
    int t = blockIdx.x * blockDim.x + threadIdx.x;
    if (t < NTt) {
        int s = s_idx[t];
        int p = atomicAdd(&g_cur[s], 1);
        g_perm[p] = t;
    }
}

// ------------------------- reciprocal of segment sums ----------------------
__global__ void k_inv() {
    int i = blockIdx.x * blockDim.x + threadIdx.x;
    if (i < Nn * RPk) {
        float c = g_colsum[i];
        float r = g_rowsum[i];
        g_invcol[i] = (c > 0.f) ? 1.f / c : 0.f;
        g_invrow[i] = (r > 0.f) ? 1.f / r : 0.f;
    }
}

// ------------------------- layer-1 spmm: h[s] += sum_k coef * w1[o*k] ------
__global__ void __launch_bounds__(256)
k_spmm1(const int* __restrict__ s_idx, const int* __restrict__ o_idx,
        const float* __restrict__ w1) {
    int gt = blockIdx.x * blockDim.x + threadIdx.x;
    int lane = gt & 31;
    int warp = gt >> 5;
    int sub = lane >> 3;   // edge within warp (0..3)
    int q   = lane & 7;    // float4 chunk (0..7)
    int t = warp * 4 + sub;
    if (t >= NTt) return;
    int o = o_idx[t], s = s_idx[t];
    const float* lat = &g_lat1[(size_t)t * 16];
    float4 acc = make_float4(0.f, 0.f, 0.f, 0.f);
#pragma unroll
    for (int k = 0; k < 16; k++) {
        int j = o * k;
        float coef = lat[k] * g_invcol[j];
        float4 w = ((const float4*)w1)[(size_t)j * 8 + q];
        acc.x += coef * w.x; acc.y += coef * w.y;
        acc.z += coef * w.z; acc.w += coef * w.w;
    }
    red4(&((float4*)g_h)[(size_t)s * 8 + q], acc);
}

// ------------------------- h = relu(h + bias1) -----------------------------
__global__ void k_relu(const float* __restrict__ bias1) {
    int i = blockIdx.x * blockDim.x + threadIdx.x;
    if (i < Nn * Ee)
        g_h[i] = fmaxf(g_h[i] + bias1[i & 31], 0.f);
}

// ------------------------- layer-2 spmm into h2 (warp per s) --------------
__global__ void __launch_bounds__(256)
k_spmm2(const int* __restrict__ o_idx) {
    __shared__ __align__(16) float stage[8][16 * 32];
    int wid = threadIdx.x >> 5, lane = threadIdx.x & 31;
    int s = blockIdx.x * 8 + wid;
    if (s >= Nn) return;
    int beg = g_off[s], end = g_off[s + 1];
    if (beg == end) return;
    float acc[16];
#pragma unroll
    for (int k = 0; k < 16; k++) acc[k] = 0.f;
    for (int p = beg; p < end; p++) {
        int t = g_perm[p];
        int o = o_idx[t];
        float hv = g_h[o * 32 + lane];
        float lv = (lane < 16) ? g_lat2[(size_t)t * 16 + lane] : 0.f;
#pragma unroll
        for (int k = 0; k < 16; k++)
            acc[k] += __shfl_sync(0xffffffffu, lv, k) * hv;
    }
    float* st = stage[wid];
#pragma unroll
    for (int k = 0; k < 16; k++) st[k * 32 + lane] = acc[k];
    __syncwarp();
#pragma unroll
    for (int it = 0; it < 4; it++) {
        int idx = it * 32 + lane;        // 0..127 over 16 rows x 8 float4
        int k = idx >> 3, q = idx & 7;
        float4 v = ((float4*)st)[idx];
        int j = s * k;                   // <= 749985
        red4(&((float4*)g_h2)[(size_t)j * 8 + q], v);
    }
}

// ------------------------- einsum + bias2: out[node] ----------------------
__global__ void __launch_bounds__(256)
k_out(const float* __restrict__ w2, const float* __restrict__ bias2,
      float* __restrict__ out) {
    extern __shared__ __align__(16) float sw2[];   // 16*32*32 = 64 KB
    for (int i = threadIdx.x; i < 16 * 32 * 32; i += 256) sw2[i] = w2[i];
    __syncthreads();
    int node = blockIdx.x * 256 + threadIdx.x;
    if (node >= Nn) return;
    unsigned long long acc2[16];
#pragma unroll
    for (int c2 = 0; c2 < 16; c2++)
        acc2[c2] = ((const unsigned long long*)bias2)[c2];
#pragma unroll 1
    for (int r = 0; r < 16; r++) {
        int j = r * Nn + node;
        float inv = g_invrow[j];
        const float4* hrow = (const float4*)&g_h2[(size_t)j * 32];
#pragma unroll
        for (int e4 = 0; e4 < 8; e4++) {
            float4 hv = hrow[e4];
            float vals[4] = { hv.x * inv, hv.y * inv, hv.z * inv, hv.w * inv };
#pragma unroll
            for (int u = 0; u < 4; u++) {
                int e = e4 * 4 + u;
                unsigned long long xs = splat2(vals[u]);
                const unsigned long long* wr =
                    (const unsigned long long*)&sw2[(r * 32 + e) * 32];
#pragma unroll
                for (int c2 = 0; c2 < 16; c2++)
                    acc2[c2] = ffma2(xs, wr[c2], acc2[c2]);
            }
        }
    }
    unsigned long long* op = (unsigned long long*)(out + (size_t)node * 32);
#pragma unroll
    for (int c2 = 0; c2 < 16; c2++) op[c2] = acc2[c2];
}

// ------------------------- launch -----------------------------------------
extern "C" void kernel_launch(void* const* d_in, const int* in_sizes, int n_in,
                              void* d_out, int out_size) {
    const int*   s_idx = (const int*)d_in[0];
    const int*   o_idx = (const int*)d_in[1];
    const float* nhots = (const float*)d_in[2];
    const float* W1a   = (const float*)d_in[3];
    const float* b1a   = (const float*)d_in[4];
    const float* W1b   = (const float*)d_in[5];
    const float* b1b   = (const float*)d_in[6];
    const float* W2a   = (const float*)d_in[7];
    const float* b2a   = (const float*)d_in[8];
    const float* W2b   = (const float*)d_in[9];
    const float* b2b   = (const float*)d_in[10];
    const float* w1    = (const float*)d_in[11];
    const float* w2    = (const float*)d_in[12];
    const float* bias1 = (const float*)d_in[13];
    const float* bias2 = (const float*)d_in[14];
    float* out = (float*)d_out;

    cudaFuncSetAttribute(k_out, cudaFuncAttributeMaxDynamicSharedMemorySize,
                         16 * 32 * 32 * (int)sizeof(float));

    k_init<<<2048, 256>>>();
    k_mlp<<<(NTt + 255) / 256, 256>>>(s_idx, o_idx, nhots,
                                      W1a, b1a, W1b, b1b,
                                      W2a, b2a, W2b, b2b);
    k_scan<<<1, 1024>>>();
    k_scatter<<<(NTt + 255) / 256, 256>>>(s_idx);
    k_inv<<<(Nn * RPk + 255) / 256, 256>>>();
    k_spmm1<<<(NTt * 8 + 255) / 256, 256>>>(s_idx, o_idx, w1);
    k_relu<<<(Nn * Ee + 255) / 256, 256>>>(bias1);
    k_spmm2<<<(Nn + 7) / 8, 256>>>(o_idx);
    k_out<<<(Nn + 255) / 256, 256, 16 * 32 * 32 * (int)sizeof(float)>>>(w2, bias2, out);
}

// round 2
// speedup vs baseline: 1.0307x; 1.0307x over previous
#include <cuda_runtime.h>
#include <cstdint>

#define Nn  50000
#define NTt 300000
#define RPk 16
#define Ee  32
#define Cc  32

// ------------------------- device scratch (static, no allocs) -------------
__device__ float g_lat1[(size_t)NTt * RPk];        // 19.2 MB
__device__ float g_lat2[(size_t)NTt * RPk];        // 19.2 MB
__device__ float g_colsum[Nn * RPk];               // 3.2 MB
__device__ float g_rowsum[Nn * RPk];               // 3.2 MB
__device__ float g_h[Nn * Ee];                     // 6.4 MB
__device__ float g_h2[(size_t)RPk * Nn * Ee];      // 102.4 MB
__device__ int   g_deg_s[Nn];
__device__ int   g_deg_o[Nn];
__device__ int   g_off_s[Nn];
__device__ int   g_off_o[Nn];
__device__ int   g_cur_s[Nn];
__device__ int   g_cur_o[Nn];
__device__ int   g_perm_s[NTt];
__device__ int   g_perm_o[NTt];
__device__ int   g_counter[2];

// ------------------------- small helpers ----------------------------------
__device__ __forceinline__ unsigned long long splat2(float v) {
    unsigned long long r;
    asm("mov.b64 %0, {%1, %1};" : "=l"(r) : "f"(v));
    return r;
}
__device__ __forceinline__ unsigned long long ffma2(unsigned long long a,
                                                    unsigned long long b,
                                                    unsigned long long c) {
    unsigned long long d;
    asm("fma.rn.f32x2 %0, %1, %2, %3;" : "=l"(d) : "l"(a), "l"(b), "l"(c));
    return d;
}
__device__ __forceinline__ void red4(float4* a, float4 v) {
    asm volatile("red.global.add.v4.f32 [%0], {%1, %2, %3, %4};"
                 :: "l"(a), "f"(v.x), "f"(v.y), "f"(v.z), "f"(v.w) : "memory");
}
__device__ __forceinline__ void red1(float* a, float v) {
    asm volatile("red.global.add.f32 [%0], %1;" :: "l"(a), "f"(v) : "memory");
}

// ------------------------- init: zero scratch -----------------------------
__global__ void k_init() {
    size_t i = (size_t)blockIdx.x * blockDim.x + threadIdx.x;
    size_t stride = (size_t)gridDim.x * blockDim.x;
    float4 z = make_float4(0.f, 0.f, 0.f, 0.f);
    for (size_t p = i; p < (size_t)RPk * Nn * Ee / 4; p += stride)
        ((float4*)g_h2)[p] = z;
    for (size_t p = i; p < (size_t)Nn * RPk / 4; p += stride) {
        ((float4*)g_colsum)[p] = z;
        ((float4*)g_rowsum)[p] = z;
    }
    for (size_t p = i; p < (size_t)Nn * Ee / 4; p += stride)
        ((float4*)g_h)[p] = z;
    for (size_t p = i; p < Nn / 4; p += stride) {
        ((int4*)g_deg_s)[p] = make_int4(0, 0, 0, 0);
        ((int4*)g_deg_o)[p] = make_int4(0, 0, 0, 0);
    }
    if (i == 0) { g_counter[0] = 0; g_counter[1] = 0; }
}

// ------------------------- per-edge MLPs + softmax + segment sums ---------
__device__ __forceinline__ void mlp16(const float* __restrict__ nh,
                                      const float* __restrict__ Wa,
                                      const float* __restrict__ ba,
                                      const float* __restrict__ Wb,
                                      const float* __restrict__ bb,
                                      float* __restrict__ lat) {
    unsigned long long hid[32];
#pragma unroll
    for (int j = 0; j < 32; j++) hid[j] = ((const unsigned long long*)ba)[j];
#pragma unroll
    for (int i4 = 0; i4 < 16; i4++) {
        float4 v = __ldg((const float4*)nh + i4);
        float xs4[4] = { v.x, v.y, v.z, v.w };
#pragma unroll
        for (int u = 0; u < 4; u++) {
            unsigned long long xs = splat2(xs4[u]);
            const unsigned long long* wr =
                (const unsigned long long*)(Wa + (i4 * 4 + u) * 64);
#pragma unroll
            for (int j = 0; j < 32; j++) hid[j] = ffma2(xs, wr[j], hid[j]);
        }
    }
    unsigned long long acc[8];
#pragma unroll
    for (int k = 0; k < 8; k++) acc[k] = ((const unsigned long long*)bb)[k];
#pragma unroll
    for (int j = 0; j < 32; j++) {
        float2 hv = *(float2*)&hid[j];
        unsigned long long s0 = splat2(fmaxf(hv.x, 0.f));
        unsigned long long s1 = splat2(fmaxf(hv.y, 0.f));
        const unsigned long long* w0 = (const unsigned long long*)(Wb + (2 * j) * 16);
        const unsigned long long* w1 = (const unsigned long long*)(Wb + (2 * j + 1) * 16);
#pragma unroll
        for (int k = 0; k < 8; k++) acc[k] = ffma2(s1, w1[k], ffma2(s0, w0[k], acc[k]));
    }
#pragma unroll
    for (int k = 0; k < 8; k++) {
        float2 v = *(float2*)&acc[k];
        lat[2 * k] = v.x;
        lat[2 * k + 1] = v.y;
    }
}

__device__ __forceinline__ void softmax16(float* l) {
    float m = l[0];
#pragma unroll
    for (int k = 1; k < 16; k++) m = fmaxf(m, l[k]);
    float s = 0.f;
#pragma unroll
    for (int k = 0; k < 16; k++) { l[k] = __expf(l[k] - m); s += l[k]; }
    float inv = 1.f / s;
#pragma unroll
    for (int k = 0; k < 16; k++) l[k] *= inv;
}

__global__ void __launch_bounds__(256)
k_mlp(const int* __restrict__ s_idx, const int* __restrict__ o_idx,
      const float* __restrict__ nhots,
      const float* __restrict__ W1a, const float* __restrict__ b1a,
      const float* __restrict__ W1b, const float* __restrict__ b1b,
      const float* __restrict__ W2a, const float* __restrict__ b2a,
      const float* __restrict__ W2b, const float* __restrict__ b2b) {
    __shared__ __align__(16) float sW1a[64 * 64];
    __shared__ __align__(16) float sW1b[64 * 16];
    __shared__ __align__(16) float sW2a[64 * 64];
    __shared__ __align__(16) float sW2b[64 * 16];
    __shared__ __align__(16) float sb1a[64], sb2a[64];
    __shared__ __align__(16) float sb1b[16], sb2b[16];
    __shared__ float swr1[8], swr2[8];

    int tid = threadIdx.x;
    for (int i = tid; i < 64 * 64; i += 256) { sW1a[i] = W1a[i]; sW2a[i] = W2a[i]; }
    for (int i = tid; i < 64 * 16; i += 256) { sW1b[i] = W1b[i]; sW2b[i] = W2b[i]; }
    if (tid < 64) { sb1a[tid] = b1a[tid]; sb2a[tid] = b2a[tid]; }
    if (tid < 16) { sb1b[tid] = b1b[tid]; sb2b[tid] = b2b[tid]; }
    __syncthreads();

    int t = blockIdx.x * 256 + tid;
    float l1_0 = 0.f, l2_0 = 0.f;
    if (t < NTt) {
        const float* nh = nhots + (size_t)t * 64;
        int s = s_idx[t], o = o_idx[t];

        float l1[16], l2[16];
        mlp16(nh, sW1a, sb1a, sW1b, sb1b, l1);
        mlp16(nh, sW2a, sb2a, sW2b, sb2b, l2);
        softmax16(l1);
        softmax16(l2);

        float4* p1 = (float4*)&g_lat1[(size_t)t * 16];
        float4* p2 = (float4*)&g_lat2[(size_t)t * 16];
#pragma unroll
        for (int q = 0; q < 4; q++) {
            p1[q] = make_float4(l1[4 * q], l1[4 * q + 1], l1[4 * q + 2], l1[4 * q + 3]);
            p2[q] = make_float4(l2[4 * q], l2[4 * q + 1], l2[4 * q + 2], l2[4 * q + 3]);
        }
#pragma unroll
        for (int k = 1; k < 16; k++) {
            red1(&g_colsum[o * k], l1[k]);
            red1(&g_rowsum[s * k], l2[k]);
        }
        l1_0 = l1[0];
        l2_0 = l2[0];
        atomicAdd(&g_deg_s[s], 1);
        atomicAdd(&g_deg_o[o], 1);
    }
    // block-reduce the k=0 contributions (all hit bin 0)
#pragma unroll
    for (int off = 16; off; off >>= 1) {
        l1_0 += __shfl_down_sync(0xffffffffu, l1_0, off);
        l2_0 += __shfl_down_sync(0xffffffffu, l2_0, off);
    }
    int wid = tid >> 5, lane = tid & 31;
    if (lane == 0) { swr1[wid] = l1_0; swr2[wid] = l2_0; }
    __syncthreads();
    if (tid == 0) {
        float a = 0.f, b = 0.f;
#pragma unroll
        for (int i = 0; i < 8; i++) { a += swr1[i]; b += swr2[i]; }
        red1(&g_colsum[0], a);
        red1(&g_rowsum[0], b);
    }
}

// ---------------- CSR range allocation (warp-aggregated, unordered) -------
__global__ void k_alloc() {
    int i = blockIdx.x * blockDim.x + threadIdx.x;
    int lane = threadIdx.x & 31;
    int ds = (i < Nn) ? g_deg_s[i] : 0;
    int dq = (i < Nn) ? g_deg_o[i] : 0;
    int ss = ds, so = dq;
#pragma unroll
    for (int off = 1; off < 32; off <<= 1) {
        int a = __shfl_up_sync(0xffffffffu, ss, off);
        int b = __shfl_up_sync(0xffffffffu, so, off);
        if (lane >= off) { ss += a; so += b; }
    }
    int bs = 0, bo = 0;
    if (lane == 31) {
        bs = atomicAdd(&g_counter[0], ss);
        bo = atomicAdd(&g_counter[1], so);
    }
    bs = __shfl_sync(0xffffffffu, bs, 31);
    bo = __shfl_sync(0xffffffffu, bo, 31);
    if (i < Nn) {
        int es = bs + ss - ds;
        int eo = bo + so - dq;
        g_off_s[i] = es; g_cur_s[i] = es;
        g_off_o[i] = eo; g_cur_o[i] = eo;
    }
}

__global__ void k_scatter(const int* __restrict__ s_idx,
                          const int* __restrict__ o_idx) {
    int t = blockIdx.x * blockDim.x + threadIdx.x;
    if (t < NTt) {
        int s = s_idx[t], o = o_idx[t];
        g_perm_s[atomicAdd(&g_cur_s[s], 1)] = t;
        g_perm_o[atomicAdd(&g_cur_o[o], 1)] = t;
    }
}

// ------ layer-1 spmm, warp per o: weights loaded once, red into h[s] ------
__global__ void __launch_bounds__(256)
k_spmm1(const int* __restrict__ s_idx, const float* __restrict__ w1) {
    int w = (blockIdx.x * blockDim.x + threadIdx.x) >> 5;
    int lane = threadIdx.x & 31;
    if (w >= Nn) return;
    int o = w;
    int deg = g_deg_o[o];
    if (deg == 0) return;
    int beg = g_off_o[o];

    float wk[16];
#pragma unroll
    for (int k = 0; k < 16; k++) {
        int j = o * k;
        float c = g_colsum[j];                 // uniform across warp -> broadcast
        float inv = (c > 0.f) ? __frcp_rn(c) : 0.f;
        wk[k] = w1[(size_t)j * 32 + lane] * inv;
    }

    for (int p = beg; p < beg + deg; p++) {
        int t = g_perm_o[p];
        int s = s_idx[t];
        float lv = (lane < 16) ? g_lat1[(size_t)t * 16 + lane] : 0.f;
        float acc = 0.f;
#pragma unroll
        for (int k = 0; k < 16; k++)
            acc += __shfl_sync(0xffffffffu, lv, k) * wk[k];
        red1(&g_h[s * 32 + lane], acc);
    }
}

// ------------------------- h = relu(h + bias1) -----------------------------
__global__ void k_relu(const float* __restrict__ bias1) {
    int i = blockIdx.x * blockDim.x + threadIdx.x;
    if (i < Nn * Ee)
        g_h[i] = fmaxf(g_h[i] + bias1[i & 31], 0.f);
}

// ------------------------- layer-2 spmm into h2 (warp per s) --------------
__global__ void __launch_bounds__(256)
k_spmm2(const int* __restrict__ o_idx) {
    __shared__ __align__(16) float stage[8][16 * 32];
    int wid = threadIdx.x >> 5, lane = threadIdx.x & 31;
    int s = blockIdx.x * 8 + wid;
    if (s >= Nn) return;
    int deg = g_deg_s[s];
    if (deg == 0) return;
    int beg = g_off_s[s];
    float acc[16];
#pragma unroll
    for (int k = 0; k < 16; k++) acc[k] = 0.f;
    for (int p = beg; p < beg + deg; p++) {
        int t = g_perm_s[p];
        int o = o_idx[t];
        float hv = g_h[o * 32 + lane];
        float lv = (lane < 16) ? g_lat2[(size_t)t * 16 + lane] : 0.f;
#pragma unroll
        for (int k = 0; k < 16; k++)
            acc[k] += __shfl_sync(0xffffffffu, lv, k) * hv;
    }
    float* st = stage[wid];
#pragma unroll
    for (int k = 0; k < 16; k++) st[k * 32 + lane] = acc[k];
    __syncwarp();
#pragma unroll
    for (int it = 0; it < 4; it++) {
        int idx = it * 32 + lane;        // 0..127 over 16 rows x 8 float4
        int k = idx >> 3, q = idx & 7;
        float4 v = ((float4*)st)[idx];
        int j = s * k;
        red4(&((float4*)g_h2)[(size_t)j * 8 + q], v);
    }
}

// ------------------------- einsum + bias2: out[node] ----------------------
__global__ void __launch_bounds__(256)
k_out(const float* __restrict__ w2, const float* __restrict__ bias2,
      float* __restrict__ out) {
    extern __shared__ __align__(16) float sw2[];   // 16*32*32 floats = 64 KB
    for (int i = threadIdx.x; i < 16 * 32 * 32; i += 256) sw2[i] = w2[i];
    __syncthreads();
    int node = blockIdx.x * 256 + threadIdx.x;
    if (node >= Nn) return;
    unsigned long long acc2[16];
#pragma unroll
    for (int c2 = 0; c2 < 16; c2++)
        acc2[c2] = ((const unsigned long long*)bias2)[c2];
#pragma unroll 1
    for (int r = 0; r < 16; r++) {
        int j = r * Nn + node;
        float rs = g_rowsum[j];
        float inv = (rs > 0.f) ? __frcp_rn(rs) : 0.f;
        const float4* hrow = (const float4*)&g_h2[(size_t)j * 32];
#pragma unroll
        for (int e4 = 0; e4 < 8; e4++) {
            float4 hv = hrow[e4];
            float vals[4] = { hv.x * inv, hv.y * inv, hv.z * inv, hv.w * inv };
#pragma unroll
            for (int u = 0; u < 4; u++) {
                int e = e4 * 4 + u;
                unsigned long long xs = splat2(vals[u]);
                const unsigned long long* wr =
                    (const unsigned long long*)&sw2[(r * 32 + e) * 32];
#pragma unroll
                for (int c2 = 0; c2 < 16; c2++)
                    acc2[c2] = ffma2(xs, wr[c2], acc2[c2]);
            }
        }
    }
    unsigned long long* op = (unsigned long long*)(out + (size_t)node * 32);
#pragma unroll
    for (int c2 = 0; c2 < 16; c2++) op[c2] = acc2[c2];
}

// ------------------------- launch -----------------------------------------
extern "C" void kernel_launch(void* const* d_in, const int* in_sizes, int n_in,
                              void* d_out, int out_size) {
    const int*   s_idx = (const int*)d_in[0];
    const int*   o_idx = (const int*)d_in[1];
    const float* nhots = (const float*)d_in[2];
    const float* W1a   = (const float*)d_in[3];
    const float* b1a   = (const float*)d_in[4];
    const float* W1b   = (const float*)d_in[5];
    const float* b1b   = (const float*)d_in[6];
    const float* W2a   = (const float*)d_in[7];
    const float* b2a   = (const float*)d_in[8];
    const float* W2b   = (const float*)d_in[9];
    const float* b2b   = (const float*)d_in[10];
    const float* w1    = (const float*)d_in[11];
    const float* w2    = (const float*)d_in[12];
    const float* bias1 = (const float*)d_in[13];
    const float* bias2 = (const float*)d_in[14];
    float* out = (float*)d_out;

    cudaFuncSetAttribute(k_out, cudaFuncAttributeMaxDynamicSharedMemorySize,
                         16 * 32 * 32 * (int)sizeof(float));

    k_init<<<2048, 256>>>();
    k_mlp<<<(NTt + 255) / 256, 256>>>(s_idx, o_idx, nhots,
                                      W1a, b1a, W1b, b1b,
                                      W2a, b2a, W2b, b2b);
    k_alloc<<<(Nn + 255) / 256, 256>>>();
    k_scatter<<<(NTt + 255) / 256, 256>>>(s_idx, o_idx);
    k_spmm1<<<(Nn * 32 + 255) / 256, 256>>>(s_idx, w1);
    k_relu<<<(Nn * Ee + 255) / 256, 256>>>(bias1);
    k_spmm2<<<(Nn + 7) / 8, 256>>>(o_idx);
    k_out<<<(Nn + 255) / 256, 256, 16 * 32 * 32 * (int)sizeof(float)>>>(w2, bias2, out);
}